// round 10
// baseline (speedup 1.0000x reference)
#include <cuda_runtime.h>

#define BSZ   256     // batch rows
#define NN    4096    // n
#define TOPK  15      // k
#define ITERS 200
#define TPB   256     // threads per CTA (main kernel)
#define PAIRS 8       // packed f32x2 pairs per thread (16 j's)
#define NHALF 512     // half-row partials from k_rowred
#define RED_PITCH 272 // 256 + 16 to kill bank conflicts in stage-2 reads

__device__ float g_pmx[NHALF];
__device__ float g_pmn[NHALF];
__device__ int   g_ph[NHALF];

// ---- packed fp32x2 helpers (Blackwell f32x2 pipe) ----
__device__ __forceinline__ unsigned long long pk2(float lo, float hi) {
    unsigned long long r;
    asm("mov.b64 %0,{%1,%2};" : "=l"(r) : "f"(lo), "f"(hi));
    return r;
}
__device__ __forceinline__ void upk2(float& lo, float& hi, unsigned long long v) {
    asm("mov.b64 {%0,%1},%2;" : "=f"(lo), "=f"(hi) : "l"(v));
}
#define FMA2(d,a,b,c) asm("fma.rn.f32x2 %0,%1,%2,%3;" : "=l"(d) : "l"(a), "l"(b), "l"(c))
#define MUL2(d,a,b)   asm("mul.rn.f32x2 %0,%1,%2;"    : "=l"(d) : "l"(a), "l"(b))
#define ADD2(d,a,b)   asm("add.rn.f32x2 %0,%1,%2;"    : "=l"(d) : "l"(a), "l"(b))
#define RCPF(d,a)     asm("rcp.approx.f32 %0,%1;"     : "=f"(d) : "f"(a))

// ---------------- pre-pass: per-HALF-row max / min(no -inf) / has(-inf) ----------------
// grid = 512, block = 256; each CTA reduces 2048 elements (half a row).
__global__ void k_rowred(const float4* __restrict__ S4) {
    __shared__ float smx[256], smn[256];
    __shared__ int   sh[256];
    int hb = blockIdx.x, t = threadIdx.x;
    // 2048 elems = 512 float4; 2 per thread, both issued before processing (MLP)
    float4 a = S4[(size_t)hb * 512 + t];
    float4 c = S4[(size_t)hb * 512 + 256 + t];
    float mx = __int_as_float(0xff800000);
    float mn = __int_as_float(0x7f800000);
    int h = 0;
    float vv[8] = {a.x, a.y, a.z, a.w, c.x, c.y, c.z, c.w};
#pragma unroll
    for (int q = 0; q < 8; q++) {
        float v = vv[q];
        mx = fmaxf(mx, v);
        if (isinf(v) && v < 0.0f) h = 1;
        else mn = fminf(mn, v);
    }
    smx[t] = mx; smn[t] = mn; sh[t] = h;
    __syncthreads();
    for (int o = 128; o; o >>= 1) {
        if (t < o) {
            smx[t] = fmaxf(smx[t], smx[t + o]);
            smn[t] = fminf(smn[t], smn[t + o]);
            sh[t] |= sh[t + o];
        }
        __syncthreads();
    }
    if (t == 0) { g_pmx[hb] = smx[0]; g_pmn[hb] = smn[0]; g_ph[hb] = sh[0]; }
}

// ---------------- main Sinkhorn kernel: 1 CTA per batch row ----------------
// mu-folded linear-domain separable Sinkhorn:
//   r_j  = sum_p cc'[p] q_j^p        (Horner, 15 packed FMA)
//   z_j  = rcp(r_j)                  (MUFU)
//   S_p  = sum_j z_j q_j^p           (stride-8 ladder: 7 MUL + 8 ADD + 8 FMA)
//   cc'[p>=1] = 1/S_p ; cc'[0] = (n-k)/S_0
// Early exit when coefficients repeat bitwise (period 1, or period 2 with
// parity matching iteration 199) -> remaining iterations are identities.
// Output: out[b,j,15-p] = z_j * cc'[p] * q_j^p,  p = 1..15
__global__ void __launch_bounds__(TPB, 2) k_sink(const float* __restrict__ S,
                                                 float* __restrict__ out) {
    __shared__ float2 coef[16];
    __shared__ float2 cprev[16];
    __shared__ float  red[16 * RED_PITCH];
    __shared__ int    convflag[2];
    __shared__ float  pmx[256], pmn[256];
    __shared__ int    ph[256];
    __shared__ float  spar[4];  // k2q, lml, fill, has(as float flag)

    const int b = blockIdx.x, t = threadIdx.x;

    // ---- global-scalar reduction (every CTA, redundant but cheap) ----
    pmx[t] = fmaxf(g_pmx[t], g_pmx[t + 256]);
    pmn[t] = fminf(g_pmn[t], g_pmn[t + 256]);
    ph[t]  = g_ph[t] | g_ph[t + 256];
    __syncthreads();
    for (int o = 128; o; o >>= 1) {
        if (t < o) {
            pmx[t] = fmaxf(pmx[t], pmx[t + o]);
            pmn[t] = fminf(pmn[t], pmn[t + o]);
            ph[t] |= ph[t + o];
        }
        __syncthreads();
    }
    if (t == 0) {
        float mx = pmx[0], mn = pmn[0];
        int has = ph[0];
        float fill = mn - (mx - mn);
        float em = has ? fminf(mn, fill) : mn;
        float eM = mx;
        // Cmax over s in {em,eM}, a in {0,15}: max of convex pieces -> endpoints
        float d1 = em - 15.0f, d3 = eM - 15.0f;
        float Cmax = fmaxf(fmaxf(em * em, d1 * d1), fmaxf(eM * eM, d3 * d3));
        float lam  = 1.0f / (0.1f * Cmax);      // 1 / (eps * Cmax)
        const float L2E = 1.4426950408889634f;
        spar[0] = 2.0f * lam * L2E;             // q_j = exp2(k2q * s_j)
        spar[1] = lam * L2E;                    // cc0'[p] = n * exp2(-lml p^2)
        spar[2] = fill;
        spar[3] = has ? 1.0f : 0.0f;
        convflag[0] = 3; convflag[1] = 3;
    }
    __syncthreads();
    const float k2q  = spar[0];
    const float lml  = spar[1];
    const float fill = spar[2];
    const int   has  = (spar[3] != 0.0f);

    const float* Sr = S + (size_t)b * NN;

    // ---- prologue: q_j and q_j^8 (one exp2 per element, ever) ----
    unsigned long long q2[PAIRS], q8[PAIRS];
#pragma unroll
    for (int jj = 0; jj < PAIRS; jj++) {
        float v0 = Sr[t + (2 * jj)     * TPB];
        float v1 = Sr[t + (2 * jj + 1) * TPB];
        if (has) {
            if (isinf(v0) && v0 < 0.0f) v0 = fill;
            if (isinf(v1) && v1 < 0.0f) v1 = fill;
        }
        float q0 = exp2f(k2q * v0), q1 = exp2f(k2q * v1);
        q2[jj] = pk2(q0, q1);
        float a0 = q0 * q0, a1 = q1 * q1;       // q^2
        a0 *= a0; a1 *= a1;                     // q^4
        a0 *= a0; a1 *= a1;                     // q^8
        q8[jj] = pk2(a0, a1);
    }
    // initial coefficients: cc'[p] = n * exp(-lam p^2) = exp2(12 - lml p^2)
    if (t < 16) {
        float cb = exp2f(12.0f - lml * (float)(t * t));
        coef[t] = make_float2(cb, cb);
    }
    __syncthreads();

    unsigned int prev1b = 0x7fffffffu, prev2b = 0x7fffffffu;  // leader-local history

    // ---- Sinkhorn iterations ----
    for (int it = 0; it < ITERS; ++it) {
        unsigned long long cc[16];
#pragma unroll
        for (int pp = 0; pp < 16; pp++)
            cc[pp] = *reinterpret_cast<const unsigned long long*>(coef + pp);

        unsigned long long m[16];
#pragma unroll
        for (int pp = 0; pp < 16; pp++) m[pp] = 0ull;

#pragma unroll
        for (int jj = 0; jj < PAIRS; jj++) {
            // Horner: r = sum_p cc[p] * q^p
            unsigned long long r = cc[15];
#pragma unroll
            for (int pp = 14; pp >= 0; pp--) FMA2(r, r, q2[jj], cc[pp]);
            float rl, rh; upk2(rl, rh, r);
            float zl, zh; RCPF(zl, rl); RCPF(zh, rh);
            unsigned long long y = pk2(zl, zh);
            // stride-8 power-sum ladder
            ADD2(m[0], m[0], y);
            FMA2(m[8], y, q8[jj], m[8]);
#pragma unroll
            for (int pp = 1; pp < 8; pp++) {
                MUL2(y, y, q2[jj]);
                ADD2(m[pp], m[pp], y);
                FMA2(m[pp + 8], y, q8[jj], m[pp + 8]);
            }
        }

        // ---- cross-CTA reduction of the 16 power sums ----
#pragma unroll
        for (int pp = 0; pp < 16; pp++) {
            float lo, hi; upk2(lo, hi, m[pp]);
            red[pp * RED_PITCH + t] = lo + hi;
        }
        __syncthreads();
        {
            int pp = t >> 4, c0 = t & 15;
            const float* rp = red + pp * RED_PITCH + c0;
            float s = 0.0f;
#pragma unroll
            for (int k = 0; k < 16; k++) s += rp[k * 16];
#pragma unroll
            for (int off = 8; off; off >>= 1) s += __shfl_xor_sync(0xffffffffu, s, off);
            if (c0 == 0) {
                float v = __fdividef((pp == 0) ? (float)(NN - TOPK) : 1.0f, s);
                unsigned int vb = __float_as_uint(v);
                int fl = (vb == prev1b ? 1 : 0) | (vb == prev2b ? 2 : 0);
                prev2b = prev1b; prev1b = vb;
                cprev[pp] = coef[pp];                   // C_{it-1} for epilogue z
                coef[pp]  = make_float2(v, v);
                atomicAnd(&convflag[it & 1], fl);
                if (t == 0) convflag[(it + 1) & 1] = 3; // reset other buffer
            }
        }
        __syncthreads();
        int fl = convflag[it & 1];
        if ((fl & 1) || ((fl & 2) && (((ITERS - 1 - it) & 1) == 0))) break;
    }

    // ---- epilogue: recompute z from C_{last-1}, emit A ----
    unsigned long long cp[16];
    float ncc[16];
#pragma unroll
    for (int pp = 0; pp < 16; pp++)
        cp[pp] = *reinterpret_cast<const unsigned long long*>(cprev + pp);
#pragma unroll
    for (int pp = 1; pp < 16; pp++) ncc[pp] = coef[pp].x;

#pragma unroll
    for (int jj = 0; jj < PAIRS; jj++) {
        unsigned long long r = cp[15];
#pragma unroll
        for (int pp = 14; pp >= 0; pp--) FMA2(r, r, q2[jj], cp[pp]);
        float rl, rh; upk2(rl, rh, r);
        float zl, zh; RCPF(zl, rl); RCPF(zh, rh);
        float ql, qh; upk2(ql, qh, q2[jj]);
        {
            float* o = out + ((size_t)b * NN + (t + (2 * jj) * TPB)) * TOPK;
            float y = zl;
#pragma unroll
            for (int pp = 1; pp < 16; pp++) { y *= ql; o[15 - pp] = ncc[pp] * y; }
        }
        {
            float* o = out + ((size_t)b * NN + (t + (2 * jj + 1) * TPB)) * TOPK;
            float y = zh;
#pragma unroll
            for (int pp = 1; pp < 16; pp++) { y *= qh; o[15 - pp] = ncc[pp] * y; }
        }
    }
}

extern "C" void kernel_launch(void* const* d_in, const int* in_sizes, int n_in,
                              void* d_out, int out_size) {
    const float* S = (const float*)d_in[0];
    float* out = (float*)d_out;
    k_rowred<<<NHALF, 256>>>((const float4*)S);
    k_sink<<<BSZ, TPB>>>(S, out);
}

// round 11
// speedup vs baseline: 1.0169x; 1.0169x over previous
#include <cuda_runtime.h>

#define BSZ   256     // batch rows
#define NN    4096    // n
#define TOPK  15      // k
#define ITERS 200
#define TPB   256     // threads per CTA (main kernel)
#define PAIRS 8       // packed f32x2 pairs per thread (16 j's)
#define NHALF 512     // half-row partials from k_rowred
#define RED_PITCH 272 // 256 + 16 to kill bank conflicts in stage-2 reads

__device__ float g_pmx[NHALF];
__device__ float g_pmn[NHALF];
__device__ int   g_ph[NHALF];

// ---- packed fp32x2 helpers (Blackwell f32x2 pipe) ----
__device__ __forceinline__ unsigned long long pk2(float lo, float hi) {
    unsigned long long r;
    asm("mov.b64 %0,{%1,%2};" : "=l"(r) : "f"(lo), "f"(hi));
    return r;
}
__device__ __forceinline__ void upk2(float& lo, float& hi, unsigned long long v) {
    asm("mov.b64 {%0,%1},%2;" : "=f"(lo), "=f"(hi) : "l"(v));
}
#define FMA2(d,a,b,c) asm("fma.rn.f32x2 %0,%1,%2,%3;" : "=l"(d) : "l"(a), "l"(b), "l"(c))
#define MUL2(d,a,b)   asm("mul.rn.f32x2 %0,%1,%2;"    : "=l"(d) : "l"(a), "l"(b))
#define ADD2(d,a,b)   asm("add.rn.f32x2 %0,%1,%2;"    : "=l"(d) : "l"(a), "l"(b))
#define RCPF(d,a)     asm("rcp.approx.f32 %0,%1;"     : "=f"(d) : "f"(a))

// ---------------- pre-pass: per-HALF-row max / min(no -inf) / has(-inf) ----------------
// grid = 512, block = 256; each CTA reduces 2048 elements (half a row).
__global__ void k_rowred(const float4* __restrict__ S4) {
    __shared__ float smx[256], smn[256];
    __shared__ int   sh[256];
    int hb = blockIdx.x, t = threadIdx.x;
    // 2048 elems = 512 float4; 2 per thread, both issued before processing (MLP)
    float4 a = S4[(size_t)hb * 512 + t];
    float4 c = S4[(size_t)hb * 512 + 256 + t];
    float mx = __int_as_float(0xff800000);
    float mn = __int_as_float(0x7f800000);
    int h = 0;
    float vv[8] = {a.x, a.y, a.z, a.w, c.x, c.y, c.z, c.w};
#pragma unroll
    for (int q = 0; q < 8; q++) {
        float v = vv[q];
        mx = fmaxf(mx, v);
        if (isinf(v) && v < 0.0f) h = 1;
        else mn = fminf(mn, v);
    }
    smx[t] = mx; smn[t] = mn; sh[t] = h;
    __syncthreads();
    for (int o = 128; o; o >>= 1) {
        if (t < o) {
            smx[t] = fmaxf(smx[t], smx[t + o]);
            smn[t] = fminf(smn[t], smn[t + o]);
            sh[t] |= sh[t + o];
        }
        __syncthreads();
    }
    if (t == 0) { g_pmx[hb] = smx[0]; g_pmn[hb] = smn[0]; g_ph[hb] = sh[0]; }
}

// ---------------- main Sinkhorn kernel: 1 CTA per batch row ----------------
// mu-folded linear-domain separable Sinkhorn:
//   r_j  = sum_p cc'[p] q_j^p        (Horner, 15 packed FMA)
//   z_j  = rcp(r_j)                  (MUFU)
//   S_p  = sum_j z_j q_j^p           (stride-8 ladder: 7 MUL + 8 ADD + 8 FMA)
//   cc'[p>=1] = 1/S_p ; cc'[0] = (n-k)/S_0
// Early exit when coefficients repeat bitwise (period 1, or period 2 with
// parity matching iteration 199) -> remaining iterations are identities.
// Output: out[b,j,15-p] = z_j * cc'[p] * q_j^p,  p = 1..15
__global__ void __launch_bounds__(TPB, 2) k_sink(const float* __restrict__ S,
                                                 float* __restrict__ out) {
    __shared__ float2 coef[16];
    __shared__ float2 cprev[16];
    __shared__ float  red[16 * RED_PITCH];
    __shared__ int    convflag[2];
    __shared__ float  pmx[256], pmn[256];
    __shared__ int    ph[256];
    __shared__ float  spar[4];  // k2q, lml, fill, has(as float flag)

    const int b = blockIdx.x, t = threadIdx.x;

    // ---- global-scalar reduction (every CTA, redundant but cheap) ----
    pmx[t] = fmaxf(g_pmx[t], g_pmx[t + 256]);
    pmn[t] = fminf(g_pmn[t], g_pmn[t + 256]);
    ph[t]  = g_ph[t] | g_ph[t + 256];
    __syncthreads();
    for (int o = 128; o; o >>= 1) {
        if (t < o) {
            pmx[t] = fmaxf(pmx[t], pmx[t + o]);
            pmn[t] = fminf(pmn[t], pmn[t + o]);
            ph[t] |= ph[t + o];
        }
        __syncthreads();
    }
    if (t == 0) {
        float mx = pmx[0], mn = pmn[0];
        int has = ph[0];
        float fill = mn - (mx - mn);
        float em = has ? fminf(mn, fill) : mn;
        float eM = mx;
        // Cmax over s in {em,eM}, a in {0,15}: max of convex pieces -> endpoints
        float d1 = em - 15.0f, d3 = eM - 15.0f;
        float Cmax = fmaxf(fmaxf(em * em, d1 * d1), fmaxf(eM * eM, d3 * d3));
        float lam  = 1.0f / (0.1f * Cmax);      // 1 / (eps * Cmax)
        const float L2E = 1.4426950408889634f;
        spar[0] = 2.0f * lam * L2E;             // q_j = exp2(k2q * s_j)
        spar[1] = lam * L2E;                    // cc0'[p] = n * exp2(-lml p^2)
        spar[2] = fill;
        spar[3] = has ? 1.0f : 0.0f;
        convflag[0] = 3; convflag[1] = 3;
    }
    __syncthreads();
    const float k2q  = spar[0];
    const float lml  = spar[1];
    const float fill = spar[2];
    const int   has  = (spar[3] != 0.0f);

    const float* Sr = S + (size_t)b * NN;

    // ---- prologue: q_j and q_j^8 (one exp2 per element, ever) ----
    unsigned long long q2[PAIRS], q8[PAIRS];
#pragma unroll
    for (int jj = 0; jj < PAIRS; jj++) {
        float v0 = Sr[t + (2 * jj)     * TPB];
        float v1 = Sr[t + (2 * jj + 1) * TPB];
        if (has) {
            if (isinf(v0) && v0 < 0.0f) v0 = fill;
            if (isinf(v1) && v1 < 0.0f) v1 = fill;
        }
        float q0 = exp2f(k2q * v0), q1 = exp2f(k2q * v1);
        q2[jj] = pk2(q0, q1);
        float a0 = q0 * q0, a1 = q1 * q1;       // q^2
        a0 *= a0; a1 *= a1;                     // q^4
        a0 *= a0; a1 *= a1;                     // q^8
        q8[jj] = pk2(a0, a1);
    }
    // initial coefficients: cc'[p] = n * exp(-lam p^2) = exp2(12 - lml p^2)
    if (t < 16) {
        float cb = exp2f(12.0f - lml * (float)(t * t));
        coef[t] = make_float2(cb, cb);
    }
    __syncthreads();

    unsigned int prev1b = 0x7fffffffu, prev2b = 0x7fffffffu;  // leader-local history

    // ---- Sinkhorn iterations ----
    for (int it = 0; it < ITERS; ++it) {
        unsigned long long cc[16];
#pragma unroll
        for (int pp = 0; pp < 16; pp++)
            cc[pp] = *reinterpret_cast<const unsigned long long*>(coef + pp);

        unsigned long long m[16];
#pragma unroll
        for (int pp = 0; pp < 16; pp++) m[pp] = 0ull;

#pragma unroll
        for (int jj = 0; jj < PAIRS; jj++) {
            // Horner: r = sum_p cc[p] * q^p
            unsigned long long r = cc[15];
#pragma unroll
            for (int pp = 14; pp >= 0; pp--) FMA2(r, r, q2[jj], cc[pp]);
            float rl, rh; upk2(rl, rh, r);
            float zl, zh; RCPF(zl, rl); RCPF(zh, rh);
            unsigned long long y = pk2(zl, zh);
            // stride-8 power-sum ladder
            ADD2(m[0], m[0], y);
            FMA2(m[8], y, q8[jj], m[8]);
#pragma unroll
            for (int pp = 1; pp < 8; pp++) {
                MUL2(y, y, q2[jj]);
                ADD2(m[pp], m[pp], y);
                FMA2(m[pp + 8], y, q8[jj], m[pp + 8]);
            }
        }

        // ---- cross-CTA reduction of the 16 power sums ----
#pragma unroll
        for (int pp = 0; pp < 16; pp++) {
            float lo, hi; upk2(lo, hi, m[pp]);
            red[pp * RED_PITCH + t] = lo + hi;
        }
        __syncthreads();
        {
            int pp = t >> 4, c0 = t & 15;
            const float* rp = red + pp * RED_PITCH + c0;
            float s = 0.0f;
#pragma unroll
            for (int k = 0; k < 16; k++) s += rp[k * 16];
#pragma unroll
            for (int off = 8; off; off >>= 1) s += __shfl_xor_sync(0xffffffffu, s, off);
            if (c0 == 0) {
                float v = __fdividef((pp == 0) ? (float)(NN - TOPK) : 1.0f, s);
                unsigned int vb = __float_as_uint(v);
                int fl = (vb == prev1b ? 1 : 0) | (vb == prev2b ? 2 : 0);
                prev2b = prev1b; prev1b = vb;
                cprev[pp] = coef[pp];                   // C_{it-1} for epilogue z
                coef[pp]  = make_float2(v, v);
                atomicAnd(&convflag[it & 1], fl);
                if (t == 0) convflag[(it + 1) & 1] = 3; // reset other buffer
            }
        }
        __syncthreads();
        int fl = convflag[it & 1];
        if ((fl & 1) || ((fl & 2) && (((ITERS - 1 - it) & 1) == 0))) break;
    }

    // ---- epilogue: recompute z from C_{last-1}, emit A ----
    unsigned long long cp[16];
    float ncc[16];
#pragma unroll
    for (int pp = 0; pp < 16; pp++)
        cp[pp] = *reinterpret_cast<const unsigned long long*>(cprev + pp);
#pragma unroll
    for (int pp = 1; pp < 16; pp++) ncc[pp] = coef[pp].x;

#pragma unroll
    for (int jj = 0; jj < PAIRS; jj++) {
        unsigned long long r = cp[15];
#pragma unroll
        for (int pp = 14; pp >= 0; pp--) FMA2(r, r, q2[jj], cp[pp]);
        float rl, rh; upk2(rl, rh, r);
        float zl, zh; RCPF(zl, rl); RCPF(zh, rh);
        float ql, qh; upk2(ql, qh, q2[jj]);
        {
            float* o = out + ((size_t)b * NN + (t + (2 * jj) * TPB)) * TOPK;
            float y = zl;
#pragma unroll
            for (int pp = 1; pp < 16; pp++) { y *= ql; o[15 - pp] = ncc[pp] * y; }
        }
        {
            float* o = out + ((size_t)b * NN + (t + (2 * jj + 1) * TPB)) * TOPK;
            float y = zh;
#pragma unroll
            for (int pp = 1; pp < 16; pp++) { y *= qh; o[15 - pp] = ncc[pp] * y; }
        }
    }
}

extern "C" void kernel_launch(void* const* d_in, const int* in_sizes, int n_in,
                              void* d_out, int out_size) {
    const float* S = (const float*)d_in[0];
    float* out = (float*)d_out;
    k_rowred<<<NHALF, 256>>>((const float4*)S);
    k_sink<<<BSZ, TPB>>>(S, out);
}